// round 7
// baseline (speedup 1.0000x reference)
#include <cuda_runtime.h>
#include <cuda_bf16.h>
#include <cstdint>

#define NPTS 262144
#define DIMS 10
#define DD   286            // comb(13,3)
#define KT   288            // K padded: 18 ksteps of 16
#define ROWE 296            // row stride in bf16 elems (592 B)
#define ROWB 592            // row stride bytes
#define NB   32             // N columns per streamed B chunk
#define NCH  9              // 288 / 32 chunks
#define CHB  (NB * ROWB * 2)   // bytes per chunk (Bh + Bl) = 37888
#define BM   128

typedef unsigned long long ull;

// Flat Veronese scratch: v_flat[r*NPTS + c]; q-vector n = contiguous chunk
// [n*286,(n+1)*286) — this layout IS the reference reshape. Keep it.
__device__ float g_scratch[(size_t)DD * NPTS];
// B images, exact smem byte layout: [chunk 9][Bh 32x592B | Bl 32x592B].
__device__ uint4 g_B[NCH * CHB / 16];

// ---------------------------------------------------------------------------
// k_prepB: B[n][k] = M_inv[k][n] (zero-padded to 288x288), bf16 hi+residual,
// written at final smem offsets.
// ---------------------------------------------------------------------------
__global__ void k_prepB(const float* __restrict__ M) {
    int t = blockIdx.x * blockDim.x + threadIdx.x;
    if (t >= KT * KT) return;
    int n = t / KT, k = t - n * KT;
    float v = (n < DD && k < DD) ? M[k * DD + n] : 0.0f;
    __nv_bfloat16 vh = __float2bfloat16(v);
    __nv_bfloat16 vl = __float2bfloat16(v - __bfloat162float(vh));
    __nv_bfloat16* B = reinterpret_cast<__nv_bfloat16*>(g_B);
    size_t cb = (size_t)(n >> 5) * (CHB / 2);
    size_t off = cb + (size_t)(n & 31) * ROWE + k;
    B[off] = vh;
    B[off + NB * ROWE] = vl;
}

// ---------------------------------------------------------------------------
// k_veronese: row order matches reference _exponent_nk exactly.
// ---------------------------------------------------------------------------
__device__ __forceinline__ float4 f4mul(float4 a, float4 b) {
    return make_float4(a.x * b.x, a.y * b.y, a.z * b.z, a.w * b.w);
}
__global__ void k_veronese(const float* __restrict__ X) {
    int t = blockIdx.x * blockDim.x + threadIdx.x;
    int c = t * 4;
    float4 y[DIMS];
#pragma unroll
    for (int k = 0; k < DIMS; k++)
        y[k] = *reinterpret_cast<const float4*>(X + (size_t)k * NPTS + c);
    int r = 0;
    *reinterpret_cast<float4*>(g_scratch + (size_t)r * NPTS + c) =
        make_float4(1.f, 1.f, 1.f, 1.f);
    r++;
#pragma unroll
    for (int j = 0; j < DIMS; j++) {
        *reinterpret_cast<float4*>(g_scratch + (size_t)r * NPTS + c) = y[j];
        r++;
    }
#pragma unroll
    for (int j = 0; j < DIMS; j++)
#pragma unroll
        for (int a = j; a < DIMS; a++) {
            *reinterpret_cast<float4*>(g_scratch + (size_t)r * NPTS + c) =
                f4mul(y[j], y[a]);
            r++;
        }
#pragma unroll
    for (int j = 0; j < DIMS; j++)
#pragma unroll
        for (int a = j; a < DIMS; a++) {
            float4 t2 = f4mul(y[j], y[a]);
#pragma unroll
            for (int b = a; b < DIMS; b++) {
                *reinterpret_cast<float4*>(g_scratch + (size_t)r * NPTS + c) =
                    f4mul(t2, y[b]);
                r++;
            }
        }
}

// ---------------------------------------------------------------------------
// Base-ISA PTX helpers.
// ---------------------------------------------------------------------------
__device__ __forceinline__ void ldsm4(uint32_t r[4], uint32_t addr) {
    asm volatile(
        "ldmatrix.sync.aligned.m8n8.x4.shared.b16 {%0,%1,%2,%3}, [%4];"
        : "=r"(r[0]), "=r"(r[1]), "=r"(r[2]), "=r"(r[3]) : "r"(addr));
}
__device__ __forceinline__ void mma_bf16(float c[4], const uint32_t a[4],
                                         uint32_t b0, uint32_t b1) {
    asm volatile(
        "mma.sync.aligned.m16n8k16.row.col.f32.bf16.bf16.f32 "
        "{%0,%1,%2,%3}, {%4,%5,%6,%7}, {%8,%9}, {%0,%1,%2,%3};"
        : "+f"(c[0]), "+f"(c[1]), "+f"(c[2]), "+f"(c[3])
        : "r"(a[0]), "r"(a[1]), "r"(a[2]), "r"(a[3]), "r"(b0), "r"(b1));
}
__device__ __forceinline__ void bulk_g2s(uint32_t dst, const void* src,
                                         uint32_t bytes, uint32_t mbar) {
    asm volatile(
        "cp.async.bulk.shared::cta.global.mbarrier::complete_tx::bytes "
        "[%0], [%1], %2, [%3];"
        :: "r"(dst), "l"(src), "r"(bytes), "r"(mbar) : "memory");
}
__device__ __forceinline__ void mbar_init(uint32_t mbar, uint32_t cnt) {
    asm volatile("mbarrier.init.shared.b64 [%0], %1;" :: "r"(mbar), "r"(cnt)
                 : "memory");
}
__device__ __forceinline__ void mbar_expect(uint32_t mbar, uint32_t bytes) {
    asm volatile("mbarrier.arrive.expect_tx.shared.b64 _, [%0], %1;"
                 :: "r"(mbar), "r"(bytes) : "memory");
}
__device__ __forceinline__ void mbar_arrive(uint32_t mbar) {
    asm volatile("mbarrier.arrive.shared.b64 _, [%0];" :: "r"(mbar)
                 : "memory");
}
__device__ __forceinline__ void mbar_wait(uint32_t mbar, uint32_t parity) {
    asm volatile(
        "{\n\t.reg .pred P1;\n\t"
        "W_%=:\n\t"
        "mbarrier.try_wait.parity.acquire.cta.shared::cta.b64 P1, [%0], %1, 0x989680;\n\t"
        "@P1 bra.uni D_%=;\n\t"
        "bra.uni W_%=;\n\t"
        "D_%=:\n\t}"
        :: "r"(mbar), "r"(parity) : "memory");
}
__device__ __forceinline__ uint32_t cvt2bf(float hi, float lo) {
    uint32_t r;
    asm("cvt.rn.bf16x2.f32 %0, %1, %2;" : "=r"(r) : "f"(hi), "f"(lo));
    return r;
}

// SMEM map
constexpr int SM_FULL0 = 0, SM_EMPTY0 = 16;
constexpr int SM_AH = 1024;
constexpr int SM_AL = SM_AH + BM * ROWB;       // 76800
constexpr int SM_B  = SM_AL + BM * ROWB;       // 152576
constexpr int SMEM_TOTAL = SM_B + 2 * CHB;     // 228352

// ---------------------------------------------------------------------------
// k_main: A-split fill -> double-buffered B stream + 3-product HMMA GEMM.
// 12 independent accumulators (4 n-groups x 3 products) + pipelined frags.
// ---------------------------------------------------------------------------
__global__ __launch_bounds__(256, 1) void k_main(float* __restrict__ out) {
    extern __shared__ char sm[];
    const uint32_t smb = (uint32_t)__cvta_generic_to_shared(sm);
    const int tid = threadIdx.x, w = tid >> 5, lane = tid & 31;

    if (tid == 0) {
        mbar_init(smb + SM_FULL0, 1);
        mbar_init(smb + SM_FULL0 + 8, 1);
        mbar_init(smb + SM_EMPTY0, 256);
        mbar_init(smb + SM_EMPTY0 + 8, 256);
    }
    __syncthreads();
    // Kick chunk 0 copy first — overlaps with the A conversion below.
    if (tid == 0) {
        mbar_expect(smb + SM_FULL0, CHB);
        bulk_g2s(smb + SM_B, g_B, CHB, smb + SM_FULL0);
    }

    // ---- A fill: warp w builds rows 16w..16w+15 (hi/lo bf16 split) ----
    {
        const float* src = g_scratch + (size_t)blockIdx.x * (BM * DD);
#pragma unroll
        for (int rr = 0; rr < 16; rr++) {
            const int r = w * 16 + rr;
            const float* qr = src + (size_t)r * DD;
            char* ah = sm + SM_AH + r * ROWB;
            char* al = sm + SM_AL + r * ROWB;
            for (int ip = lane; ip < 144; ip += 32) {
                float q0 = 0.f, q1 = 0.f;
                if (ip < 143) {
                    float2 v = *reinterpret_cast<const float2*>(qr + 2 * ip);
                    q0 = v.x; q1 = v.y;
                }
                uint32_t h2 = cvt2bf(q1, q0);
                float h0 = __uint_as_float(h2 << 16);
                float h1 = __uint_as_float(h2 & 0xffff0000u);
                uint32_t l2 = cvt2bf(q1 - h1, q0 - h0);
                *reinterpret_cast<uint32_t*>(ah + ip * 4) = h2;
                *reinterpret_cast<uint32_t*>(al + ip * 4) = l2;
            }
        }
    }
    __syncthreads();   // A complete for all warps

    const uint32_t aRow = smb + SM_AH + (w * 16 + (lane & 15)) * ROWB +
                          (lane >> 4) * 16;
    const uint32_t bOff = (((lane >> 4) & 1) * 8 + (lane & 7)) * ROWB +
                          ((lane >> 3) & 1) * 16;

    float out0 = 0.f, out1 = 0.f;
    const int r0 = w * 16 + (lane >> 2);
    const uint32_t qh0 = smb + SM_AH + r0 * ROWB + (lane & 3) * 4;
    const uint32_t ql0 = smb + SM_AL + r0 * ROWB + (lane & 3) * 4;

    for (int c = 0; c < NCH; c++) {
        const int b = c & 1;
        if (tid == 0 && c + 1 < NCH) {
            const int b2 = (c + 1) & 1;
            if (c >= 1)
                mbar_wait(smb + SM_EMPTY0 + 8 * b2, ((c - 1) >> 1) & 1);
            mbar_expect(smb + SM_FULL0 + 8 * b2, CHB);
            bulk_g2s(smb + SM_B + b2 * CHB,
                     reinterpret_cast<const char*>(g_B) + (size_t)(c + 1) * CHB,
                     CHB, smb + SM_FULL0 + 8 * b2);
        }
        mbar_wait(smb + SM_FULL0 + 8 * b, (c >> 1) & 1);

        const uint32_t bh = smb + SM_B + b * CHB + bOff;
        const uint32_t bl = bh + NB * ROWB;

        // 12 independent accumulators: C[ngroup(2 n16) * 2(n8) * ... ]
        // layout: C[p][ng][4], p = product (ah*bh, ah*bl, al*bh), ng = n8 0..3
        float C[3][4][4];
#pragma unroll
        for (int p = 0; p < 3; p++)
#pragma unroll
            for (int g = 0; g < 4; g++)
#pragma unroll
                for (int u = 0; u < 4; u++) C[p][g][u] = 0.f;

        // Pipelined fragments: [buf][...]
        uint32_t fah[2][4], fal[2][4];
        uint32_t fh0[2][4], fh1[2][4], fl0[2][4], fl1[2][4];
        ldsm4(fah[0], aRow);
        ldsm4(fal[0], aRow + (SM_AL - SM_AH));
        ldsm4(fh0[0], bh);
        ldsm4(fh1[0], bh + 16 * ROWB);
        ldsm4(fl0[0], bl);
        ldsm4(fl1[0], bl + 16 * ROWB);

#pragma unroll
        for (int k = 0; k < 18; k++) {
            const int cur = k & 1, nxt = cur ^ 1;
            if (k < 17) {
                const uint32_t ko = (k + 1) * 32;
                ldsm4(fah[nxt], aRow + ko);
                ldsm4(fal[nxt], aRow + (SM_AL - SM_AH) + ko);
                ldsm4(fh0[nxt], bh + ko);
                ldsm4(fh1[nxt], bh + 16 * ROWB + ko);
                ldsm4(fl0[nxt], bl + ko);
                ldsm4(fl1[nxt], bl + 16 * ROWB + ko);
            }
            // Product 0: ah * bh  (4 distinct accumulators)
            mma_bf16(C[0][0], fah[cur], fh0[cur][0], fh0[cur][1]);
            mma_bf16(C[0][1], fah[cur], fh0[cur][2], fh0[cur][3]);
            mma_bf16(C[0][2], fah[cur], fh1[cur][0], fh1[cur][1]);
            mma_bf16(C[0][3], fah[cur], fh1[cur][2], fh1[cur][3]);
            // Product 1: ah * bl
            mma_bf16(C[1][0], fah[cur], fl0[cur][0], fl0[cur][1]);
            mma_bf16(C[1][1], fah[cur], fl0[cur][2], fl0[cur][3]);
            mma_bf16(C[1][2], fah[cur], fl1[cur][0], fl1[cur][1]);
            mma_bf16(C[1][3], fah[cur], fl1[cur][2], fl1[cur][3]);
            // Product 2: al * bh
            mma_bf16(C[2][0], fal[cur], fh0[cur][0], fh0[cur][1]);
            mma_bf16(C[2][1], fal[cur], fh0[cur][2], fh0[cur][3]);
            mma_bf16(C[2][2], fal[cur], fh1[cur][0], fh1[cur][1]);
            mma_bf16(C[2][3], fal[cur], fh1[cur][2], fh1[cur][3]);
        }
        mbar_arrive(smb + SM_EMPTY0 + 8 * b);

        // ---- Fused epilogue: out += (C0+C1+C2) ∘ q over 32 columns ----
        const int jb = c * 32;
#pragma unroll
        for (int nc = 0; nc < 4; nc++) {
            const uint32_t jo = (jb + nc * 8) * 2;
            uint32_t vh, vl, wh, wl;
            asm volatile("ld.shared.b32 %0, [%1];" : "=r"(vh) : "r"(qh0 + jo));
            asm volatile("ld.shared.b32 %0, [%1];" : "=r"(vl) : "r"(ql0 + jo));
            asm volatile("ld.shared.b32 %0, [%1];" : "=r"(wh)
                         : "r"(qh0 + 8 * ROWB + jo));
            asm volatile("ld.shared.b32 %0, [%1];" : "=r"(wl)
                         : "r"(ql0 + 8 * ROWB + jo));
            float qe = __uint_as_float(vh << 16) + __uint_as_float(vl << 16);
            float qo = __uint_as_float(vh & 0xffff0000u) +
                       __uint_as_float(vl & 0xffff0000u);
            float re = __uint_as_float(wh << 16) + __uint_as_float(wl << 16);
            float ro = __uint_as_float(wh & 0xffff0000u) +
                       __uint_as_float(wl & 0xffff0000u);
            float t0 = C[0][nc][0] + C[1][nc][0] + C[2][nc][0];
            float t1 = C[0][nc][1] + C[1][nc][1] + C[2][nc][1];
            float t2 = C[0][nc][2] + C[1][nc][2] + C[2][nc][2];
            float t3 = C[0][nc][3] + C[1][nc][3] + C[2][nc][3];
            out0 = fmaf(t0, qe, out0);
            out0 = fmaf(t1, qo, out0);
            out1 = fmaf(t2, re, out1);
            out1 = fmaf(t3, ro, out1);
        }
    }

    out0 += __shfl_xor_sync(0xffffffffu, out0, 1);
    out0 += __shfl_xor_sync(0xffffffffu, out0, 2);
    out1 += __shfl_xor_sync(0xffffffffu, out1, 1);
    out1 += __shfl_xor_sync(0xffffffffu, out1, 2);
    if ((lane & 3) == 0) {
        out[blockIdx.x * BM + r0]     = out0;
        out[blockIdx.x * BM + r0 + 8] = out1;
    }
}

// ---------------------------------------------------------------------------
// Launch
// ---------------------------------------------------------------------------
extern "C" void kernel_launch(void* const* d_in, const int* in_sizes, int n_in,
                              void* d_out, int out_size) {
    const float* X = (const float*)d_in[0];
    const float* M = (const float*)d_in[1];
    float* out = (float*)d_out;

    k_prepB<<<(KT * KT + 255) / 256, 256>>>(M);
    k_veronese<<<(NPTS / 4) / 256, 256>>>(X);

    cudaFuncSetAttribute(k_main, cudaFuncAttributeMaxDynamicSharedMemorySize,
                         SMEM_TOTAL);
    k_main<<<NPTS / BM, 256, SMEM_TOTAL>>>(out);
}

// round 8
// speedup vs baseline: 1.1495x; 1.1495x over previous
#include <cuda_runtime.h>
#include <cuda_bf16.h>
#include <cstdint>

#define NPTS 262144
#define DIMS 10
#define DD   286            // comb(13,3)
#define KT   288            // K padded: 18 ksteps of 16
#define ROWE 296            // row stride in bf16 elems (592 B)
#define ROWB 592            // row stride bytes
#define NB   32             // N columns per streamed B chunk
#define NCH  9              // 288 / 32 chunks
#define CHB  (NB * ROWB * 2)   // bytes per chunk (Bh + Bl) = 37888
#define BM   128

typedef unsigned long long ull;

// Flat Veronese scratch: v_flat[r*NPTS + c]; q-vector n = contiguous chunk
// [n*286,(n+1)*286) — this layout IS the reference reshape. Keep it.
__device__ float g_scratch[(size_t)DD * NPTS];
// B images of the SYMMETRIZED UPPER-TRIANGULAR S:
//   S[k][n] = (k<n: M[k][n]+M[n][k]; k==n: M[n][n]; k>n: 0)
// exact smem byte layout: [chunk 9][Bh 32x592B | Bl 32x592B].
__device__ uint4 g_B[NCH * CHB / 16];

// ---------------------------------------------------------------------------
// k_prepB: B[n][k] = S[k][n], bf16 hi+residual, at final smem offsets.
// ---------------------------------------------------------------------------
__global__ void k_prepB(const float* __restrict__ M) {
    int t = blockIdx.x * blockDim.x + threadIdx.x;
    if (t >= KT * KT) return;
    int n = t / KT, k = t - n * KT;
    float v = 0.0f;
    if (n < DD && k < DD) {
        if (k < n)       v = M[k * DD + n] + M[n * DD + k];
        else if (k == n) v = M[n * DD + n];
    }
    __nv_bfloat16 vh = __float2bfloat16(v);
    __nv_bfloat16 vl = __float2bfloat16(v - __bfloat162float(vh));
    __nv_bfloat16* B = reinterpret_cast<__nv_bfloat16*>(g_B);
    size_t cb = (size_t)(n >> 5) * (CHB / 2);
    size_t off = cb + (size_t)(n & 31) * ROWE + k;
    B[off] = vh;
    B[off + NB * ROWE] = vl;
}

// ---------------------------------------------------------------------------
// k_veronese: row order matches reference _exponent_nk exactly.
// ---------------------------------------------------------------------------
__device__ __forceinline__ float4 f4mul(float4 a, float4 b) {
    return make_float4(a.x * b.x, a.y * b.y, a.z * b.z, a.w * b.w);
}
__global__ void k_veronese(const float* __restrict__ X) {
    int t = blockIdx.x * blockDim.x + threadIdx.x;
    int c = t * 4;
    float4 y[DIMS];
#pragma unroll
    for (int k = 0; k < DIMS; k++)
        y[k] = *reinterpret_cast<const float4*>(X + (size_t)k * NPTS + c);
    int r = 0;
    *reinterpret_cast<float4*>(g_scratch + (size_t)r * NPTS + c) =
        make_float4(1.f, 1.f, 1.f, 1.f);
    r++;
#pragma unroll
    for (int j = 0; j < DIMS; j++) {
        *reinterpret_cast<float4*>(g_scratch + (size_t)r * NPTS + c) = y[j];
        r++;
    }
#pragma unroll
    for (int j = 0; j < DIMS; j++)
#pragma unroll
        for (int a = j; a < DIMS; a++) {
            *reinterpret_cast<float4*>(g_scratch + (size_t)r * NPTS + c) =
                f4mul(y[j], y[a]);
            r++;
        }
#pragma unroll
    for (int j = 0; j < DIMS; j++)
#pragma unroll
        for (int a = j; a < DIMS; a++) {
            float4 t2 = f4mul(y[j], y[a]);
#pragma unroll
            for (int b = a; b < DIMS; b++) {
                *reinterpret_cast<float4*>(g_scratch + (size_t)r * NPTS + c) =
                    f4mul(t2, y[b]);
                r++;
            }
        }
}

// ---------------------------------------------------------------------------
// Base-ISA PTX helpers.
// ---------------------------------------------------------------------------
__device__ __forceinline__ void ldsm4(uint32_t r[4], uint32_t addr) {
    asm volatile(
        "ldmatrix.sync.aligned.m8n8.x4.shared.b16 {%0,%1,%2,%3}, [%4];"
        : "=r"(r[0]), "=r"(r[1]), "=r"(r[2]), "=r"(r[3]) : "r"(addr));
}
__device__ __forceinline__ void mma_bf16(float c[4], const uint32_t a[4],
                                         uint32_t b0, uint32_t b1) {
    asm volatile(
        "mma.sync.aligned.m16n8k16.row.col.f32.bf16.bf16.f32 "
        "{%0,%1,%2,%3}, {%4,%5,%6,%7}, {%8,%9}, {%0,%1,%2,%3};"
        : "+f"(c[0]), "+f"(c[1]), "+f"(c[2]), "+f"(c[3])
        : "r"(a[0]), "r"(a[1]), "r"(a[2]), "r"(a[3]), "r"(b0), "r"(b1));
}
__device__ __forceinline__ void bulk_g2s(uint32_t dst, const void* src,
                                         uint32_t bytes, uint32_t mbar) {
    asm volatile(
        "cp.async.bulk.shared::cta.global.mbarrier::complete_tx::bytes "
        "[%0], [%1], %2, [%3];"
        :: "r"(dst), "l"(src), "r"(bytes), "r"(mbar) : "memory");
}
__device__ __forceinline__ void mbar_init(uint32_t mbar, uint32_t cnt) {
    asm volatile("mbarrier.init.shared.b64 [%0], %1;" :: "r"(mbar), "r"(cnt)
                 : "memory");
}
__device__ __forceinline__ void mbar_expect(uint32_t mbar, uint32_t bytes) {
    asm volatile("mbarrier.arrive.expect_tx.shared.b64 _, [%0], %1;"
                 :: "r"(mbar), "r"(bytes) : "memory");
}
__device__ __forceinline__ void mbar_arrive(uint32_t mbar) {
    asm volatile("mbarrier.arrive.shared.b64 _, [%0];" :: "r"(mbar)
                 : "memory");
}
__device__ __forceinline__ void mbar_wait(uint32_t mbar, uint32_t parity) {
    asm volatile(
        "{\n\t.reg .pred P1;\n\t"
        "W_%=:\n\t"
        "mbarrier.try_wait.parity.acquire.cta.shared::cta.b64 P1, [%0], %1, 0x989680;\n\t"
        "@P1 bra.uni D_%=;\n\t"
        "bra.uni W_%=;\n\t"
        "D_%=:\n\t}"
        :: "r"(mbar), "r"(parity) : "memory");
}
__device__ __forceinline__ uint32_t cvt2bf(float hi, float lo) {
    uint32_t r;
    asm("cvt.rn.bf16x2.f32 %0, %1, %2;" : "=r"(r) : "f"(hi), "f"(lo));
    return r;
}

// SMEM map
constexpr int SM_FULL0 = 0, SM_EMPTY0 = 16;
constexpr int SM_AH = 1024;
constexpr int SM_AL = SM_AH + BM * ROWB;       // 76800
constexpr int SM_B  = SM_AL + BM * ROWB;       // 152576
constexpr int SMEM_TOTAL = SM_B + 2 * CHB;     // 228352

// ---------------------------------------------------------------------------
// k_main: A-split fill -> double-buffered B stream + TRIANGULAR 3-product
// HMMA GEMM (chunk c needs only ksteps 0..2c+1) + fused T·q epilogue.
// ---------------------------------------------------------------------------
__global__ __launch_bounds__(256, 1) void k_main(float* __restrict__ out) {
    extern __shared__ char sm[];
    const uint32_t smb = (uint32_t)__cvta_generic_to_shared(sm);
    const int tid = threadIdx.x, w = tid >> 5, lane = tid & 31;

    if (tid == 0) {
        mbar_init(smb + SM_FULL0, 1);
        mbar_init(smb + SM_FULL0 + 8, 1);
        mbar_init(smb + SM_EMPTY0, 256);
        mbar_init(smb + SM_EMPTY0 + 8, 256);
    }
    __syncthreads();
    if (tid == 0) {    // kick chunk 0 copy; overlaps A conversion
        mbar_expect(smb + SM_FULL0, CHB);
        bulk_g2s(smb + SM_B, g_B, CHB, smb + SM_FULL0);
    }

    // ---- A fill: warp w builds rows 16w..16w+15 (hi/lo bf16 split) ----
    {
        const float* src = g_scratch + (size_t)blockIdx.x * (BM * DD);
#pragma unroll
        for (int rr = 0; rr < 16; rr++) {
            const int r = w * 16 + rr;
            const float* qr = src + (size_t)r * DD;
            char* ah = sm + SM_AH + r * ROWB;
            char* al = sm + SM_AL + r * ROWB;
            for (int ip = lane; ip < 144; ip += 32) {
                float q0 = 0.f, q1 = 0.f;
                if (ip < 143) {
                    float2 v = *reinterpret_cast<const float2*>(qr + 2 * ip);
                    q0 = v.x; q1 = v.y;
                }
                uint32_t h2 = cvt2bf(q1, q0);
                float h0 = __uint_as_float(h2 << 16);
                float h1 = __uint_as_float(h2 & 0xffff0000u);
                uint32_t l2 = cvt2bf(q1 - h1, q0 - h0);
                *reinterpret_cast<uint32_t*>(ah + ip * 4) = h2;
                *reinterpret_cast<uint32_t*>(al + ip * 4) = l2;
            }
        }
    }
    __syncthreads();

    const uint32_t aRow = smb + SM_AH + (w * 16 + (lane & 15)) * ROWB +
                          (lane >> 4) * 16;
    const uint32_t bOff = (((lane >> 4) & 1) * 8 + (lane & 7)) * ROWB +
                          ((lane >> 3) & 1) * 16;

    float out0 = 0.f, out1 = 0.f;
    const int r0 = w * 16 + (lane >> 2);
    const uint32_t qh0 = smb + SM_AH + r0 * ROWB + (lane & 3) * 4;
    const uint32_t ql0 = smb + SM_AL + r0 * ROWB + (lane & 3) * 4;

    for (int c = 0; c < NCH; c++) {
        const int b = c & 1;
        if (tid == 0 && c + 1 < NCH) {
            const int b2 = (c + 1) & 1;
            if (c >= 1)
                mbar_wait(smb + SM_EMPTY0 + 8 * b2, ((c - 1) >> 1) & 1);
            mbar_expect(smb + SM_FULL0 + 8 * b2, CHB);
            bulk_g2s(smb + SM_B + b2 * CHB,
                     reinterpret_cast<const char*>(g_B) + (size_t)(c + 1) * CHB,
                     CHB, smb + SM_FULL0 + 8 * b2);
        }
        mbar_wait(smb + SM_FULL0 + 8 * b, (c >> 1) & 1);

        const uint32_t bh = smb + SM_B + b * CHB + bOff;
        const uint32_t bl = bh + NB * ROWB;

        float C[3][4][4];
#pragma unroll
        for (int p = 0; p < 3; p++)
#pragma unroll
            for (int g = 0; g < 4; g++)
#pragma unroll
                for (int u = 0; u < 4; u++) C[p][g][u] = 0.f;

        // Triangular bound: S[k][n]=0 for k>n; chunk c needs ksteps 0..2c+1.
        const int kmax = 2 * c + 2;

        uint32_t fah[2][4], fal[2][4];
        uint32_t fh0[2][4], fh1[2][4], fl0[2][4], fl1[2][4];
        ldsm4(fah[0], aRow);
        ldsm4(fal[0], aRow + (SM_AL - SM_AH));
        ldsm4(fh0[0], bh);
        ldsm4(fh1[0], bh + 16 * ROWB);
        ldsm4(fl0[0], bl);
        ldsm4(fl1[0], bl + 16 * ROWB);

#pragma unroll 2
        for (int k = 0; k < kmax; k++) {
            const int cur = k & 1, nxt = cur ^ 1;
            if (k + 1 < kmax) {
                const uint32_t ko = (k + 1) * 32;
                ldsm4(fah[nxt], aRow + ko);
                ldsm4(fal[nxt], aRow + (SM_AL - SM_AH) + ko);
                ldsm4(fh0[nxt], bh + ko);
                ldsm4(fh1[nxt], bh + 16 * ROWB + ko);
                ldsm4(fl0[nxt], bl + ko);
                ldsm4(fl1[nxt], bl + 16 * ROWB + ko);
            }
            mma_bf16(C[0][0], fah[cur], fh0[cur][0], fh0[cur][1]);
            mma_bf16(C[0][1], fah[cur], fh0[cur][2], fh0[cur][3]);
            mma_bf16(C[0][2], fah[cur], fh1[cur][0], fh1[cur][1]);
            mma_bf16(C[0][3], fah[cur], fh1[cur][2], fh1[cur][3]);
            mma_bf16(C[1][0], fah[cur], fl0[cur][0], fl0[cur][1]);
            mma_bf16(C[1][1], fah[cur], fl0[cur][2], fl0[cur][3]);
            mma_bf16(C[1][2], fah[cur], fl1[cur][0], fl1[cur][1]);
            mma_bf16(C[1][3], fah[cur], fl1[cur][2], fl1[cur][3]);
            mma_bf16(C[2][0], fal[cur], fh0[cur][0], fh0[cur][1]);
            mma_bf16(C[2][1], fal[cur], fh0[cur][2], fh0[cur][3]);
            mma_bf16(C[2][2], fal[cur], fh1[cur][0], fh1[cur][1]);
            mma_bf16(C[2][3], fal[cur], fh1[cur][2], fh1[cur][3]);
        }
        mbar_arrive(smb + SM_EMPTY0 + 8 * b);

        // ---- Fused epilogue: out += (C0+C1+C2) ∘ q over 32 columns ----
        const int jb = c * 32;
#pragma unroll
        for (int nc = 0; nc < 4; nc++) {
            const uint32_t jo = (jb + nc * 8) * 2;
            uint32_t vh, vl, wh, wl;
            asm volatile("ld.shared.b32 %0, [%1];" : "=r"(vh) : "r"(qh0 + jo));
            asm volatile("ld.shared.b32 %0, [%1];" : "=r"(vl) : "r"(ql0 + jo));
            asm volatile("ld.shared.b32 %0, [%1];" : "=r"(wh)
                         : "r"(qh0 + 8 * ROWB + jo));
            asm volatile("ld.shared.b32 %0, [%1];" : "=r"(wl)
                         : "r"(ql0 + 8 * ROWB + jo));
            float qe = __uint_as_float(vh << 16) + __uint_as_float(vl << 16);
            float qo = __uint_as_float(vh & 0xffff0000u) +
                       __uint_as_float(vl & 0xffff0000u);
            float re = __uint_as_float(wh << 16) + __uint_as_float(wl << 16);
            float ro = __uint_as_float(wh & 0xffff0000u) +
                       __uint_as_float(wl & 0xffff0000u);
            float t0 = C[0][nc][0] + C[1][nc][0] + C[2][nc][0];
            float t1 = C[0][nc][1] + C[1][nc][1] + C[2][nc][1];
            float t2 = C[0][nc][2] + C[1][nc][2] + C[2][nc][2];
            float t3 = C[0][nc][3] + C[1][nc][3] + C[2][nc][3];
            out0 = fmaf(t0, qe, out0);
            out0 = fmaf(t1, qo, out0);
            out1 = fmaf(t2, re, out1);
            out1 = fmaf(t3, ro, out1);
        }
    }

    out0 += __shfl_xor_sync(0xffffffffu, out0, 1);
    out0 += __shfl_xor_sync(0xffffffffu, out0, 2);
    out1 += __shfl_xor_sync(0xffffffffu, out1, 1);
    out1 += __shfl_xor_sync(0xffffffffu, out1, 2);
    if ((lane & 3) == 0) {
        out[blockIdx.x * BM + r0]     = out0;
        out[blockIdx.x * BM + r0 + 8] = out1;
    }
}

// ---------------------------------------------------------------------------
// Launch
// ---------------------------------------------------------------------------
extern "C" void kernel_launch(void* const* d_in, const int* in_sizes, int n_in,
                              void* d_out, int out_size) {
    const float* X = (const float*)d_in[0];
    const float* M = (const float*)d_in[1];
    float* out = (float*)d_out;

    k_prepB<<<(KT * KT + 255) / 256, 256>>>(M);
    k_veronese<<<(NPTS / 4) / 256, 256>>>(X);

    cudaFuncSetAttribute(k_main, cudaFuncAttributeMaxDynamicSharedMemorySize,
                         SMEM_TOTAL);
    k_main<<<NPTS / BM, 256, SMEM_TOTAL>>>(out);
}

// round 9
// speedup vs baseline: 2.2623x; 1.9681x over previous
#include <cuda_runtime.h>
#include <cuda_bf16.h>
#include <cstdint>

#define NPTS 262144         // 2^18 points
#define CSH  18             // log2(NPTS)
#define CMSK 0x3FFFFu
#define DIMS 10
#define DD   286            // comb(13,3)
#define KT   288            // K padded: 18 ksteps of 16
#define ROWE 296            // A row stride in bf16 elems (592 B)
#define ROWB 592            // A row stride bytes
#define NB   32             // N columns per streamed B chunk
#define NCH  9              // 288 / 32 chunks
#define CHB  (NB * ROWB * 2)   // bytes per chunk (Bh + Bl) = 37888
#define BM   128
#define ONEI 10             // sentinel index -> ones row

typedef unsigned long long ull;

// B images of symmetrized upper-tri S (S[k][n] = k<n: M[k][n]+M[n][k];
// k==n: M[n][n]; else 0), exact smem layout [chunk 9][Bh 32x592 | Bl 32x592].
__device__ uint4 g_B[NCH * CHB / 16];
__device__ float g_ones[NPTS];
// Monomial index table, reference _exponent_nk order: i0 | i1<<8 | i2<<16.
__device__ uint32_t g_tab[DD];

// ---------------------------------------------------------------------------
// k_prep: B image + ones row + monomial table (fused, 1024 blocks x 256).
// ---------------------------------------------------------------------------
__global__ void k_prep(const float* __restrict__ M) {
    int idx = blockIdx.x * blockDim.x + threadIdx.x;
    if (idx < NPTS) g_ones[idx] = 1.0f;
    if (idx < KT * KT) {
        int n = idx / KT, k = idx - n * KT;
        float v = 0.0f;
        if (n < DD && k < DD) {
            if (k < n)       v = M[k * DD + n] + M[n * DD + k];
            else if (k == n) v = M[n * DD + n];
        }
        __nv_bfloat16 vh = __float2bfloat16(v);
        __nv_bfloat16 vl = __float2bfloat16(v - __bfloat162float(vh));
        __nv_bfloat16* B = reinterpret_cast<__nv_bfloat16*>(g_B);
        size_t cb = (size_t)(n >> 5) * (CHB / 2);
        size_t off = cb + (size_t)(n & 31) * ROWE + k;
        B[off] = vh;
        B[off + NB * ROWE] = vl;
    }
    if (idx == 0) {   // table in reference enumeration order
        int r = 0;
        g_tab[r++] = ONEI | (ONEI << 8) | (ONEI << 16);
        for (int j = 0; j < DIMS; j++)
            g_tab[r++] = j | (ONEI << 8) | (ONEI << 16);
        for (int j = 0; j < DIMS; j++)
            for (int a = j; a < DIMS; a++)
                g_tab[r++] = j | (a << 8) | (ONEI << 16);
        for (int j = 0; j < DIMS; j++)
            for (int a = j; a < DIMS; a++)
                for (int b = a; b < DIMS; b++)
                    g_tab[r++] = j | (a << 8) | (b << 16);
    }
}

// ---------------------------------------------------------------------------
// Base-ISA PTX helpers.
// ---------------------------------------------------------------------------
__device__ __forceinline__ void ldsm4(uint32_t r[4], uint32_t addr) {
    asm volatile(
        "ldmatrix.sync.aligned.m8n8.x4.shared.b16 {%0,%1,%2,%3}, [%4];"
        : "=r"(r[0]), "=r"(r[1]), "=r"(r[2]), "=r"(r[3]) : "r"(addr));
}
__device__ __forceinline__ void mma_bf16(float c[4], const uint32_t a[4],
                                         uint32_t b0, uint32_t b1) {
    asm volatile(
        "mma.sync.aligned.m16n8k16.row.col.f32.bf16.bf16.f32 "
        "{%0,%1,%2,%3}, {%4,%5,%6,%7}, {%8,%9}, {%0,%1,%2,%3};"
        : "+f"(c[0]), "+f"(c[1]), "+f"(c[2]), "+f"(c[3])
        : "r"(a[0]), "r"(a[1]), "r"(a[2]), "r"(a[3]), "r"(b0), "r"(b1));
}
__device__ __forceinline__ void bulk_g2s(uint32_t dst, const void* src,
                                         uint32_t bytes, uint32_t mbar) {
    asm volatile(
        "cp.async.bulk.shared::cta.global.mbarrier::complete_tx::bytes "
        "[%0], [%1], %2, [%3];"
        :: "r"(dst), "l"(src), "r"(bytes), "r"(mbar) : "memory");
}
__device__ __forceinline__ void mbar_init(uint32_t mbar, uint32_t cnt) {
    asm volatile("mbarrier.init.shared.b64 [%0], %1;" :: "r"(mbar), "r"(cnt)
                 : "memory");
}
__device__ __forceinline__ void mbar_expect(uint32_t mbar, uint32_t bytes) {
    asm volatile("mbarrier.arrive.expect_tx.shared.b64 _, [%0], %1;"
                 :: "r"(mbar), "r"(bytes) : "memory");
}
__device__ __forceinline__ void mbar_arrive(uint32_t mbar) {
    asm volatile("mbarrier.arrive.shared.b64 _, [%0];" :: "r"(mbar)
                 : "memory");
}
__device__ __forceinline__ void mbar_wait(uint32_t mbar, uint32_t parity) {
    asm volatile(
        "{\n\t.reg .pred P1;\n\t"
        "W_%=:\n\t"
        "mbarrier.try_wait.parity.acquire.cta.shared::cta.b64 P1, [%0], %1, 0x989680;\n\t"
        "@P1 bra.uni D_%=;\n\t"
        "bra.uni W_%=;\n\t"
        "D_%=:\n\t}"
        :: "r"(mbar), "r"(parity) : "memory");
}

__device__ __forceinline__ const float* mono_ptr(const float* X, uint32_t i) {
    return (i < DIMS) ? (X + (size_t)i * NPTS) : g_ones;
}

// SMEM map
constexpr int SM_FULL0 = 0, SM_EMPTY0 = 16;
constexpr int SM_AH = 1024;
constexpr int SM_AL = SM_AH + BM * ROWB;       // 76800
constexpr int SM_B  = SM_AL + BM * ROWB;       // 152576
constexpr int SMEM_TOTAL = SM_B + 2 * CHB;     // 228352

// ---------------------------------------------------------------------------
// k_main: direct A build from L2-resident x (q-vector n = 286 consecutive
// evaluations of monomial r=(n*286)>>18) -> double-buffered B stream +
// triangular 3-product HMMA GEMM + fused T·q epilogue.
// ---------------------------------------------------------------------------
__global__ __launch_bounds__(256, 1) void k_main(const float* __restrict__ X,
                                                 float* __restrict__ out) {
    extern __shared__ char sm[];
    const uint32_t smb = (uint32_t)__cvta_generic_to_shared(sm);
    const int tid = threadIdx.x, w = tid >> 5, lane = tid & 31;

    if (tid == 0) {
        mbar_init(smb + SM_FULL0, 1);
        mbar_init(smb + SM_FULL0 + 8, 1);
        mbar_init(smb + SM_EMPTY0, 256);
        mbar_init(smb + SM_EMPTY0 + 8, 256);
    }
    __syncthreads();
    if (tid == 0) {    // kick chunk 0 copy; overlaps A build
        mbar_expect(smb + SM_FULL0, CHB);
        bulk_g2s(smb + SM_B, g_B, CHB, smb + SM_FULL0);
    }

    // ---- A build: warp w builds rows 16w..16w+15 directly from x ----
#pragma unroll
    for (int rr = 0; rr < 16; rr++) {
        const int row = w * 16 + rr;
        const int n = blockIdx.x * BM + row;
        const uint32_t flat0 = (uint32_t)n * (uint32_t)DD;
        char* ah = sm + SM_AH + row * ROWB;
        char* al = sm + SM_AL + row * ROWB;
        const uint32_t c0 = flat0 & CMSK;
        if (c0 + DD <= NPTS) {          // fast path: one monomial, contiguous
            const uint32_t t = __ldg(g_tab + (flat0 >> CSH));
            const float* p0 = mono_ptr(X, t & 0xffu) + c0;
            const float* p1 = mono_ptr(X, (t >> 8) & 0xffu) + c0;
            const float* p2 = mono_ptr(X, (t >> 16) & 0xffu) + c0;
            for (int i = lane; i < DD; i += 32) {
                float v = (__ldg(p0 + i) * __ldg(p1 + i)) * __ldg(p2 + i);
                __nv_bfloat16 vh = __float2bfloat16(v);
                __nv_bfloat16 vl = __float2bfloat16(v - __bfloat162float(vh));
                *reinterpret_cast<__nv_bfloat16*>(ah + i * 2) = vh;
                *reinterpret_cast<__nv_bfloat16*>(al + i * 2) = vl;
            }
        } else {                        // rare straddle: per-element
            for (int i = lane; i < DD; i += 32) {
                const uint32_t f = flat0 + i;
                const uint32_t t = __ldg(g_tab + (f >> CSH));
                const uint32_t c = f & CMSK;
                float v = (__ldg(mono_ptr(X, t & 0xffu) + c) *
                           __ldg(mono_ptr(X, (t >> 8) & 0xffu) + c)) *
                          __ldg(mono_ptr(X, (t >> 16) & 0xffu) + c);
                __nv_bfloat16 vh = __float2bfloat16(v);
                __nv_bfloat16 vl = __float2bfloat16(v - __bfloat162float(vh));
                *reinterpret_cast<__nv_bfloat16*>(ah + i * 2) = vh;
                *reinterpret_cast<__nv_bfloat16*>(al + i * 2) = vl;
            }
        }
        if (lane < 2) {                 // zero pad i = 286, 287
            *reinterpret_cast<uint32_t*>(ah + 572) = 0u;
            *reinterpret_cast<uint32_t*>(al + 572) = 0u;
        }
    }
    __syncthreads();

    const uint32_t aRow = smb + SM_AH + (w * 16 + (lane & 15)) * ROWB +
                          (lane >> 4) * 16;
    const uint32_t bOff = (((lane >> 4) & 1) * 8 + (lane & 7)) * ROWB +
                          ((lane >> 3) & 1) * 16;

    float out0 = 0.f, out1 = 0.f;
    const int r0 = w * 16 + (lane >> 2);
    const uint32_t qh0 = smb + SM_AH + r0 * ROWB + (lane & 3) * 4;
    const uint32_t ql0 = smb + SM_AL + r0 * ROWB + (lane & 3) * 4;

    for (int c = 0; c < NCH; c++) {
        const int b = c & 1;
        if (tid == 0 && c + 1 < NCH) {
            const int b2 = (c + 1) & 1;
            if (c >= 1)
                mbar_wait(smb + SM_EMPTY0 + 8 * b2, ((c - 1) >> 1) & 1);
            mbar_expect(smb + SM_FULL0 + 8 * b2, CHB);
            bulk_g2s(smb + SM_B + b2 * CHB,
                     reinterpret_cast<const char*>(g_B) + (size_t)(c + 1) * CHB,
                     CHB, smb + SM_FULL0 + 8 * b2);
        }
        mbar_wait(smb + SM_FULL0 + 8 * b, (c >> 1) & 1);

        const uint32_t bh = smb + SM_B + b * CHB + bOff;
        const uint32_t bl = bh + NB * ROWB;

        float C[3][4][4];
#pragma unroll
        for (int p = 0; p < 3; p++)
#pragma unroll
            for (int g = 0; g < 4; g++)
#pragma unroll
                for (int u = 0; u < 4; u++) C[p][g][u] = 0.f;

        // Triangular bound: chunk c needs ksteps 0..2c+1 only.
        const int kmax = 2 * c + 2;

        uint32_t fah[2][4], fal[2][4];
        uint32_t fh0[2][4], fh1[2][4], fl0[2][4], fl1[2][4];
        ldsm4(fah[0], aRow);
        ldsm4(fal[0], aRow + (SM_AL - SM_AH));
        ldsm4(fh0[0], bh);
        ldsm4(fh1[0], bh + 16 * ROWB);
        ldsm4(fl0[0], bl);
        ldsm4(fl1[0], bl + 16 * ROWB);

#pragma unroll 2
        for (int k = 0; k < kmax; k++) {
            const int cur = k & 1, nxt = cur ^ 1;
            if (k + 1 < kmax) {
                const uint32_t ko = (k + 1) * 32;
                ldsm4(fah[nxt], aRow + ko);
                ldsm4(fal[nxt], aRow + (SM_AL - SM_AH) + ko);
                ldsm4(fh0[nxt], bh + ko);
                ldsm4(fh1[nxt], bh + 16 * ROWB + ko);
                ldsm4(fl0[nxt], bl + ko);
                ldsm4(fl1[nxt], bl + 16 * ROWB + ko);
            }
            mma_bf16(C[0][0], fah[cur], fh0[cur][0], fh0[cur][1]);
            mma_bf16(C[0][1], fah[cur], fh0[cur][2], fh0[cur][3]);
            mma_bf16(C[0][2], fah[cur], fh1[cur][0], fh1[cur][1]);
            mma_bf16(C[0][3], fah[cur], fh1[cur][2], fh1[cur][3]);
            mma_bf16(C[1][0], fah[cur], fl0[cur][0], fl0[cur][1]);
            mma_bf16(C[1][1], fah[cur], fl0[cur][2], fl0[cur][3]);
            mma_bf16(C[1][2], fah[cur], fl1[cur][0], fl1[cur][1]);
            mma_bf16(C[1][3], fah[cur], fl1[cur][2], fl1[cur][3]);
            mma_bf16(C[2][0], fal[cur], fh0[cur][0], fh0[cur][1]);
            mma_bf16(C[2][1], fal[cur], fh0[cur][2], fh0[cur][3]);
            mma_bf16(C[2][2], fal[cur], fh1[cur][0], fh1[cur][1]);
            mma_bf16(C[2][3], fal[cur], fh1[cur][2], fh1[cur][3]);
        }
        mbar_arrive(smb + SM_EMPTY0 + 8 * b);

        // ---- Fused epilogue: out += (C0+C1+C2) ∘ q over 32 columns ----
        const int jb = c * 32;
#pragma unroll
        for (int nc = 0; nc < 4; nc++) {
            const uint32_t jo = (jb + nc * 8) * 2;
            uint32_t vh, vl, wh, wl;
            asm volatile("ld.shared.b32 %0, [%1];" : "=r"(vh) : "r"(qh0 + jo));
            asm volatile("ld.shared.b32 %0, [%1];" : "=r"(vl) : "r"(ql0 + jo));
            asm volatile("ld.shared.b32 %0, [%1];" : "=r"(wh)
                         : "r"(qh0 + 8 * ROWB + jo));
            asm volatile("ld.shared.b32 %0, [%1];" : "=r"(wl)
                         : "r"(ql0 + 8 * ROWB + jo));
            float qe = __uint_as_float(vh << 16) + __uint_as_float(vl << 16);
            float qo = __uint_as_float(vh & 0xffff0000u) +
                       __uint_as_float(vl & 0xffff0000u);
            float re = __uint_as_float(wh << 16) + __uint_as_float(wl << 16);
            float ro = __uint_as_float(wh & 0xffff0000u) +
                       __uint_as_float(wl & 0xffff0000u);
            float t0 = C[0][nc][0] + C[1][nc][0] + C[2][nc][0];
            float t1 = C[0][nc][1] + C[1][nc][1] + C[2][nc][1];
            float t2 = C[0][nc][2] + C[1][nc][2] + C[2][nc][2];
            float t3 = C[0][nc][3] + C[1][nc][3] + C[2][nc][3];
            out0 = fmaf(t0, qe, out0);
            out0 = fmaf(t1, qo, out0);
            out1 = fmaf(t2, re, out1);
            out1 = fmaf(t3, ro, out1);
        }
    }

    out0 += __shfl_xor_sync(0xffffffffu, out0, 1);
    out0 += __shfl_xor_sync(0xffffffffu, out0, 2);
    out1 += __shfl_xor_sync(0xffffffffu, out1, 1);
    out1 += __shfl_xor_sync(0xffffffffu, out1, 2);
    if ((lane & 3) == 0) {
        out[blockIdx.x * BM + r0]     = out0;
        out[blockIdx.x * BM + r0 + 8] = out1;
    }
}

// ---------------------------------------------------------------------------
// Launch (2 kernels only)
// ---------------------------------------------------------------------------
extern "C" void kernel_launch(void* const* d_in, const int* in_sizes, int n_in,
                              void* d_out, int out_size) {
    const float* X = (const float*)d_in[0];   // x flat (xr[k][c] = X[k*NPTS+c])
    const float* M = (const float*)d_in[1];   // M_inv 286x286
    float* out = (float*)d_out;

    k_prep<<<NPTS / 256, 256>>>(M);

    cudaFuncSetAttribute(k_main, cudaFuncAttributeMaxDynamicSharedMemorySize,
                         SMEM_TOTAL);
    k_main<<<NPTS / BM, 256, SMEM_TOTAL>>>(X, out);
}